// round 15
// baseline (speedup 1.0000x reference)
#include <cuda_runtime.h>
#include <cuda_fp16.h>
#include <cstdint>
#include <cstddef>

// Problem sizes (fixed)
#define BB 32
#define SS 2048
#define HH 256
#define ZZ 64

#define INV_T   (0.0625f)   // 1/sqrt(256)
#define NEGINF  (-1e9f)

// ---------------- scratch (device globals; no allocations allowed) ----------
__device__ __half g_GThi[HH * HH];
__device__ __half g_GTlo[HH * HH];
__device__ __half g_dechi[(size_t)BB * SS * HH];   // compacted rows
__device__ __half g_declo[(size_t)BB * SS * HH];
__device__ __half g_ehi[(size_t)BB * SS * HH];
__device__ __half g_elo[(size_t)BB * SS * HH];
__device__ __half g_qhi[(size_t)BB * SS * HH];     // q' compact
__device__ __half g_qlo[(size_t)BB * SS * HH];
__device__ float  g_vT[(size_t)BB * ZZ * SS];      // v^T fp32, [b][d][s]
__device__ __half g_patt[(size_t)BB * SS * SS];    // p compact rows, fp16
__device__ float  g_pmax[(size_t)BB * 16 * SS];
__device__ float  g_psum[(size_t)BB * 16 * SS];
__device__ float  g_cmax[(size_t)BB * SS];
__device__ float  g_rcs[(size_t)BB * SS];
__device__ int    g_idx[(size_t)BB * SS];          // unmasked row indices
__device__ int    g_cnt[BB];
__device__ float  g_att[(size_t)BB * SS * SS];     // fallback attn buffer

// ---------------- mask dtype detection --------------------------------------
__device__ __forceinline__ bool mask_is_i32(const void* m) {
    const unsigned int* p = (const unsigned int*)m;
    unsigned int o = p[0] | p[1] | p[2] | p[3] | p[4] | p[5] | p[6] | p[7];
    return o <= 1u;
}

__device__ __forceinline__ uint32_t smem_u32(const void* p) {
    uint32_t a;
    asm("{ .reg .u64 t; cvta.to.shared.u64 t, %1; cvt.u32.u64 %0, t; }" : "=r"(a) : "l"(p));
    return a;
}

// FMA-pipe exp (no MUFU)
__device__ __forceinline__ float fexp(float x) {
    float y = fmaxf(x * 1.4426950408889634f, -126.0f);
    float r = rintf(y);
    float f = y - r;
    float p =              1.3333558146e-3f;
    p = fmaf(p, f, 9.6181291077e-3f);
    p = fmaf(p, f, 5.5504108664e-2f);
    p = fmaf(p, f, 2.4022650696e-1f);
    p = fmaf(p, f, 6.9314718056e-1f);
    p = fmaf(p, f, 1.0f);
    return __int_as_float(__float_as_int(p) + (((int)r) << 23));
}

__device__ __forceinline__ void hmma16816(float* d, const uint32_t* a, const uint32_t* b) {
    asm volatile(
        "mma.sync.aligned.m16n8k16.row.col.f32.f16.f16.f32 "
        "{%0,%1,%2,%3}, {%4,%5,%6,%7}, {%8,%9}, {%0,%1,%2,%3};"
        : "+f"(d[0]), "+f"(d[1]), "+f"(d[2]), "+f"(d[3])
        : "r"(a[0]), "r"(a[1]), "r"(a[2]), "r"(a[3]), "r"(b[0]), "r"(b[1]));
}

#define LDSM4(r, a) \
    asm volatile("ldmatrix.sync.aligned.m8n8.x4.shared.b16 {%0,%1,%2,%3}, [%4];" \
        : "=r"((r)[0]), "=r"((r)[1]), "=r"((r)[2]), "=r"((r)[3]) : "r"(a))

// streaming (evict-first) vector stores
__device__ __forceinline__ void stcs_u4(uint4* p, uint4 v) {
    asm volatile("st.global.cs.v4.u32 [%0], {%1,%2,%3,%4};"
                 :: "l"(p), "r"(v.x), "r"(v.y), "r"(v.z), "r"(v.w) : "memory");
}
__device__ __forceinline__ void stcs_f4(float4* p, float4 v) {
    asm volatile("st.global.cs.v4.f32 [%0], {%1,%2,%3,%4};"
                 :: "l"(p), "f"(v.x), "f"(v.y), "f"(v.z), "f"(v.w) : "memory");
}

// ========== compact: per-batch list of unmasked row indices ==================
__global__ __launch_bounds__(256) void compact_kernel(
    const void* __restrict__ mask, int* __restrict__ idx, int* __restrict__ cnt)
{
    const int b = blockIdx.x;
    const int t = threadIdx.x;
    const bool i32 = mask_is_i32(mask);
    const int*           mi = (const int*)mask;
    const unsigned char* mb = (const unsigned char*)mask;

    int loc[8]; int c = 0;
#pragma unroll
    for (int k = 0; k < 8; ++k) {
        const int i = t * 8 + k;
        const int v = i32 ? (mi[b * SS + i] != 0) : (mb[b * SS + i] != 0);
        loc[k] = v; c += v;
    }
    __shared__ int ps[256];
    ps[t] = c;
    __syncthreads();
    for (int off = 1; off < 256; off <<= 1) {
        int v = (t >= off) ? ps[t - off] : 0;
        __syncthreads();
        ps[t] += v;
        __syncthreads();
    }
    int base = ps[t] - c;
#pragma unroll
    for (int k = 0; k < 8; ++k)
        if (loc[k]) idx[(size_t)b * SS + (base++)] = t * 8 + k;
    const int total = ps[255];
    __syncthreads();
    for (int p = total + t; p < SS; p += 256) idx[(size_t)b * SS + p] = 0;
    if (t == 0) cnt[b] = total;
}

// ========== gather + split dec rows into compacted order =====================
__global__ __launch_bounds__(256) void gsplit_kernel(
    const float* __restrict__ in, const int* __restrict__ idx,
    const int* __restrict__ cnt, __half* __restrict__ hi, __half* __restrict__ lo)
{
    const int t = threadIdx.x;
    const int rowg = blockIdx.x * 4 + (t >> 6);
    const int b = rowg >> 11, ci = rowg & 2047;
    const int cb = cnt[b];
    const int lim = (cb + 127) & ~127;
    if (ci >= lim) return;
    const int c4 = (t & 63) * 4;
    const bool valid = ci < cb;
    const int src = idx[(size_t)b * SS + ci];
    float4 x = make_float4(0.f, 0.f, 0.f, 0.f);
    if (valid) x = *(const float4*)&in[((size_t)b * SS + src) * HH + c4];
    __half hx = __float2half_rn(x.x), hy = __float2half_rn(x.y);
    __half hz = __float2half_rn(x.z), hw = __float2half_rn(x.w);
    __half lx = __float2half_rn(x.x - __half2float(hx));
    __half ly = __float2half_rn(x.y - __half2float(hy));
    __half lz = __float2half_rn(x.z - __half2float(hz));
    __half lw = __float2half_rn(x.w - __half2float(hw));
    const size_t o = (size_t)rowg * HH + c4;
    *(__half2*)&hi[o]     = __halves2half2(hx, hy);
    *(__half2*)&hi[o + 2] = __halves2half2(hz, hw);
    *(__half2*)&lo[o]     = __halves2half2(lx, ly);
    *(__half2*)&lo[o + 2] = __halves2half2(lz, lw);
}

// ========== zero-fill masked attn rows + output rows =========================
__global__ __launch_bounds__(256) void zerofill_kernel(
    const void* __restrict__ mask, float* __restrict__ att, float* __restrict__ Out)
{
    const int b = blockIdx.y, i = blockIdx.x, t = threadIdx.x;
    const bool i32 = mask_is_i32(mask);
    const bool keep = i32 ? (((const int*)mask)[b * SS + i] != 0)
                          : (((const unsigned char*)mask)[b * SS + i] != 0);
    if (keep) return;
    const float4 z = make_float4(0.f, 0.f, 0.f, 0.f);
    float* row = att + ((size_t)b * SS + i) * SS;
#pragma unroll
    for (int u = 0; u < 2; ++u)
        stcs_f4((float4*)&row[(u * 256 + t) * 4], z);
    if (t < 16)
        stcs_f4((float4*)&Out[((size_t)b * SS + i) * ZZ + t * 4], z);
}

// ====== gmat+split: GT = Wk @ Wq^T (256x256x256), written as fp16 hi/lo ======
__global__ __launch_bounds__(256) void gmatsplit_kernel(
    const float* __restrict__ A, const float* __restrict__ B,
    __half* __restrict__ Ohi, __half* __restrict__ Olo)
{
    __shared__ float aS[32 * 65];
    __shared__ float bS[32 * 65];
    const int t  = threadIdx.x;
    const int r0 = blockIdx.y * 64;
    const int c0 = blockIdx.x * 64;

    const int lr = t >> 2;
    const int lc = (t & 3) * 8;

    float acc[4][4];
#pragma unroll
    for (int u = 0; u < 4; ++u)
#pragma unroll
        for (int v = 0; v < 4; ++v) acc[u][v] = 0.f;

    for (int k0 = 0; k0 < HH; k0 += 32) {
        __syncthreads();
        float4 a0 = *(const float4*)&A[(size_t)(r0 + lr) * HH + k0 + lc];
        float4 a1 = *(const float4*)&A[(size_t)(r0 + lr) * HH + k0 + lc + 4];
        float4 b0 = *(const float4*)&B[(size_t)(c0 + lr) * HH + k0 + lc];
        float4 b1 = *(const float4*)&B[(size_t)(c0 + lr) * HH + k0 + lc + 4];
        aS[(lc + 0) * 65 + lr] = a0.x; aS[(lc + 1) * 65 + lr] = a0.y;
        aS[(lc + 2) * 65 + lr] = a0.z; aS[(lc + 3) * 65 + lr] = a0.w;
        aS[(lc + 4) * 65 + lr] = a1.x; aS[(lc + 5) * 65 + lr] = a1.y;
        aS[(lc + 6) * 65 + lr] = a1.z; aS[(lc + 7) * 65 + lr] = a1.w;
        bS[(lc + 0) * 65 + lr] = b0.x; bS[(lc + 1) * 65 + lr] = b0.y;
        bS[(lc + 2) * 65 + lr] = b0.z; bS[(lc + 3) * 65 + lr] = b0.w;
        bS[(lc + 4) * 65 + lr] = b1.x; bS[(lc + 5) * 65 + lr] = b1.y;
        bS[(lc + 6) * 65 + lr] = b1.z; bS[(lc + 7) * 65 + lr] = b1.w;
        __syncthreads();

        const int ty = t >> 4, tx = t & 15;
#pragma unroll
        for (int kk = 0; kk < 32; ++kk) {
            float a[4], bb[4];
#pragma unroll
            for (int u = 0; u < 4; ++u) { a[u] = aS[kk * 65 + ty * 4 + u]; bb[u] = bS[kk * 65 + tx * 4 + u]; }
#pragma unroll
            for (int u = 0; u < 4; ++u)
#pragma unroll
                for (int v = 0; v < 4; ++v) acc[u][v] += a[u] * bb[v];
        }
    }

    const int ty = t >> 4, tx = t & 15;
#pragma unroll
    for (int u = 0; u < 4; ++u) {
        const size_t o = (size_t)(r0 + ty * 4 + u) * HH + c0 + tx * 4;
        __half h[4], l[4];
#pragma unroll
        for (int v = 0; v < 4; ++v) {
            h[v] = __float2half_rn(acc[u][v]);
            l[v] = __float2half_rn(acc[u][v] - __half2float(h[v]));
        }
        *(__half2*)&Ohi[o]     = __halves2half2(h[0], h[1]);
        *(__half2*)&Ohi[o + 2] = __halves2half2(h[2], h[3]);
        *(__half2*)&Olo[o]     = __halves2half2(l[0], l[1]);
        *(__half2*)&Olo[o + 2] = __halves2half2(l[2], l[3]);
    }
}

// ============ split fp32 -> fp16 hi + fp16 lo (elementwise) ==================
__global__ __launch_bounds__(256) void split_kernel(
    const float* __restrict__ in, __half* __restrict__ hi, __half* __restrict__ lo, int n4)
{
    int i = blockIdx.x * 256 + threadIdx.x;
    int stride = gridDim.x * 256;
    for (; i < n4; i += stride) {
        float4 x = ((const float4*)in)[i];
        __half hx = __float2half_rn(x.x), hy = __float2half_rn(x.y);
        __half hz = __float2half_rn(x.z), hw = __float2half_rn(x.w);
        __half lx = __float2half_rn(x.x - __half2float(hx));
        __half ly = __float2half_rn(x.y - __half2float(hy));
        __half lz = __float2half_rn(x.z - __half2float(hz));
        __half lw = __float2half_rn(x.w - __half2float(hw));
        ((__half2*)hi)[i * 2 + 0] = __halves2half2(hx, hy);
        ((__half2*)hi)[i * 2 + 1] = __halves2half2(hz, hw);
        ((__half2*)lo)[i * 2 + 0] = __halves2half2(lx, ly);
        ((__half2*)lo)[i * 2 + 1] = __halves2half2(lz, lw);
    }
}

// ========== v = latent @ Wv, written directly transposed: vT[b][d][s] ========
__global__ __launch_bounds__(256) void vprojtrans_kernel(
    const float* __restrict__ X, const float* __restrict__ Wv, float* __restrict__ vT)
{
    __shared__ float Ws[64 * 65];
    __shared__ float Xs[32 * 65];
    __shared__ float sT[32 * 65];
    const int t  = threadIdx.x;
    const int b  = blockIdx.x >> 6;
    const int s0 = (blockIdx.x & 63) * 32;
    const size_t r0 = (size_t)b * SS + s0;

#pragma unroll
    for (int u = 0; u < 16; ++u) {
        int idx = u * 256 + t; int r = idx >> 6, c = idx & 63;
        Ws[r * 65 + c] = Wv[idx];
    }
#pragma unroll
    for (int u = 0; u < 8; ++u) {
        int idx = u * 256 + t; int r = idx >> 6, c = idx & 63;
        Xs[r * 65 + c] = X[(r0 + r) * 64 + c];
    }
    __syncthreads();

    const int row = t >> 3;
    const int c0  = (t & 7) * 8;
    float acc[8];
#pragma unroll
    for (int u = 0; u < 8; ++u) acc[u] = 0.f;
#pragma unroll 8
    for (int z = 0; z < 64; ++z) {
        float a = Xs[row * 65 + z];
#pragma unroll
        for (int u = 0; u < 8; ++u) acc[u] += a * Ws[z * 65 + c0 + u];
    }
#pragma unroll
    for (int u = 0; u < 8; ++u) sT[row * 65 + c0 + u] = acc[u];
    __syncthreads();

    const int d  = t >> 2;
    const int sc = (t & 3) * 8;
    float o[8];
#pragma unroll
    for (int k = 0; k < 8; ++k) o[k] = sT[(sc + k) * 65 + d];
    float4 w0, w1;
    w0.x = o[0]; w0.y = o[1]; w0.z = o[2]; w0.w = o[3];
    w1.x = o[4]; w1.y = o[5]; w1.z = o[6]; w1.w = o[7];
    float* dst = &vT[((size_t)b * ZZ + d) * SS + s0 + sc];
    *(float4*)dst       = w0;
    *(float4*)(dst + 4) = w1;
}

// =========== Split-precision HMMA GEMM: C = A @ B^T, K=256 ===================
// CTA tile 128x128, 8 warps (2x4), warp tile 64x32, k-chunk 32, double buffer.
// Rows are COMPACTED (unmasked only); tiles past cnt early-exit.
// IS_ALIGN=1: write p = exp(logit - tilemax) fp16 (streaming) + col max/sum
// IS_ALIGN=0: (qproj) write split fp16 (qhi,qlo)
template<bool IS_ALIGN>
__global__ void __launch_bounds__(256, 2) mma_split_kernel(
    const __half* __restrict__ Ahig, const __half* __restrict__ Alog,
    const __half* __restrict__ Bhig, const __half* __restrict__ Blog,
    const int* __restrict__ cnt, __half* __restrict__ Patt,
    __half* __restrict__ Qhi, __half* __restrict__ Qlo,
    float* __restrict__ Pmax, float* __restrict__ Psum)
{
    extern __shared__ __half sm[];
    const int t    = threadIdx.x;
    const int lane = t & 31;
    const int wid  = t >> 5;
    const int warpM = wid >> 2;
    const int warpN = wid & 3;
    const int b  = IS_ALIGN ? blockIdx.z : 0;
    const int m0 = blockIdx.y * 128;
    const int n0 = blockIdx.x * 128;

    int cntb;
    if (IS_ALIGN) {
        cntb = cnt[b];
        if (m0 >= cntb) {
            if (t < 128) {
                const size_t o = ((size_t)b * 16 + blockIdx.y) * SS + n0 + t;
                Pmax[o] = -1e30f;
                Psum[o] = 0.f;
            }
            return;
        }
    } else {
        cntb = cnt[m0 >> 11];
        if ((m0 & 2047) >= cntb) return;
    }

    const size_t arow = IS_ALIGN ? ((size_t)b * SS + m0) : (size_t)m0;
    const size_t brow = IS_ALIGN ? ((size_t)b * SS + n0) : (size_t)n0;
    const __half* Ah = Ahig + arow * HH;
    const __half* Al = Alog + arow * HH;
    const __half* Bh = Bhig + brow * HH;
    const __half* Bl = Blog + brow * HH;

    const uint32_t smbase = smem_u32(sm);

    float acc[4][4][4];
#pragma unroll
    for (int mt = 0; mt < 4; ++mt)
#pragma unroll
        for (int nt = 0; nt < 4; ++nt)
#pragma unroll
            for (int r = 0; r < 4; ++r) acc[mt][nt][r] = 0.f;

    auto issue = [&](int chunk, int p) {
#pragma unroll
        for (int i = 0; i < 8; ++i) {
            const __half* basep = (i < 2) ? Ah : (i < 4) ? Al : (i < 6) ? Bh : Bl;
            const int tile = i >> 1;
            const int flat = i * 256 + t;
            const int w = flat & 511;
            const int r = w >> 2, c16 = w & 3;
            const __half* g = basep + (size_t)r * HH + chunk * 32 + c16 * 8;
            const uint32_t d = smbase +
                (uint32_t)((p * 20480 + tile * 5120 + r * 40 + c16 * 8) * 2);
            asm volatile("cp.async.cg.shared.global [%0], [%1], 16;" :: "r"(d), "l"(g));
        }
        asm volatile("cp.async.commit_group;" ::: "memory");
    };

    issue(0, 0);

    const int aRow = warpM * 64 + (lane & 7) + ((lane >> 3) & 1) * 8;
    const int aK   = (lane >> 4) * 8;
    const int bRow = warpN * 32 + (lane & 7) + (lane >> 4) * 8;
    const int bK   = ((lane >> 3) & 1) * 8;

    for (int c = 0; c < 8; ++c) {
        asm volatile("cp.async.wait_group 0;" ::: "memory");
        __syncthreads();
        if (c < 7) issue(c + 1, (c + 1) & 1);

        const int p = c & 1;
        const uint32_t abase = smbase + (uint32_t)(p * 20480 * 2);
        const uint32_t bbase = abase + 10240 * 2;

#pragma unroll
        for (int k16 = 0; k16 < 32; k16 += 16) {
            uint32_t ah[4][4], al[4][4], bh[2][4], bl[2][4];
#pragma unroll
            for (int mt = 0; mt < 4; ++mt) {
                const uint32_t adr = abase +
                    (uint32_t)(((aRow + mt * 16) * 40 + k16 + aK) * 2);
                LDSM4(ah[mt], adr);
                LDSM4(al[mt], adr + 10240);
            }
#pragma unroll
            for (int ntp = 0; ntp < 2; ++ntp) {
                const uint32_t adr = bbase +
                    (uint32_t)(((bRow + ntp * 16) * 40 + k16 + bK) * 2);
                LDSM4(bh[ntp], adr);
                LDSM4(bl[ntp], adr + 10240);
            }
#pragma unroll
            for (int mt = 0; mt < 4; ++mt)
#pragma unroll
                for (int nt = 0; nt < 4; ++nt) {
                    const uint32_t bhf[2] = { bh[nt >> 1][(nt & 1) * 2],
                                              bh[nt >> 1][(nt & 1) * 2 + 1] };
                    const uint32_t blf[2] = { bl[nt >> 1][(nt & 1) * 2],
                                              bl[nt >> 1][(nt & 1) * 2 + 1] };
                    hmma16816(acc[mt][nt], ah[mt], bhf);
                    hmma16816(acc[mt][nt], ah[mt], blf);
                    hmma16816(acc[mt][nt], al[mt], bhf);
                }
        }
    }

    // ----------------------------- epilogue ---------------------------------
    if (IS_ALIGN) {
#pragma unroll
        for (int mt = 0; mt < 4; ++mt) {
            const int ci = m0 + warpM * 64 + mt * 16 + (lane >> 2);
            const bool k0 = ci < cntb;
            const bool k8 = (ci + 8) < cntb;
#pragma unroll
            for (int nt = 0; nt < 4; ++nt) {
                acc[mt][nt][0] = k0 ? acc[mt][nt][0] * INV_T : NEGINF;
                acc[mt][nt][1] = k0 ? acc[mt][nt][1] * INV_T : NEGINF;
                acc[mt][nt][2] = k8 ? acc[mt][nt][2] * INV_T : NEGINF;
                acc[mt][nt][3] = k8 ? acc[mt][nt][3] * INV_T : NEGINF;
            }
        }

        __half* pstage = sm;                        // [128][136] halves
        float*  sMax   = (float*)(sm + 17408);      // [2][128]
        float*  sSum   = sMax + 256;                // [2][128]
        __syncthreads();

#pragma unroll
        for (int nt = 0; nt < 4; ++nt)
#pragma unroll
            for (int pp = 0; pp < 2; ++pp) {
                float lm = -3.4e38f;
#pragma unroll
                for (int mt = 0; mt < 4; ++mt) {
                    lm = fmaxf(lm, acc[mt][nt][pp]);
                    lm = fmaxf(lm, acc[mt][nt][2 + pp]);
                }
#pragma unroll
                for (int o = 4; o < 32; o <<= 1)
                    lm = fmaxf(lm, __shfl_xor_sync(0xffffffffu, lm, o));
                const int cidx = warpN * 32 + nt * 8 + (lane & 3) * 2 + pp;
                if ((lane >> 2) == 0) sMax[warpM * 128 + cidx] = lm;
            }
        __syncthreads();

#pragma unroll
        for (int nt = 0; nt < 4; ++nt) {
            const int cidx0 = warpN * 32 + nt * 8 + (lane & 3) * 2;
            const float cmv0 = fmaxf(sMax[cidx0],     sMax[128 + cidx0]);
            const float cmv1 = fmaxf(sMax[cidx0 + 1], sMax[128 + cidx0 + 1]);
            float ls0 = 0.f, ls1 = 0.f;
#pragma unroll
            for (int mt = 0; mt < 4; ++mt) {
                const int il = warpM * 64 + mt * 16 + (lane >> 2);
                float p00 = fexp(acc[mt][nt][0] - cmv0);
                float p01 = fexp(acc[mt][nt][1] - cmv1);
                float p80 = fexp(acc[mt][nt][2] - cmv0);
                float p81 = fexp(acc[mt][nt][3] - cmv1);
                ls0 += p00 + p80;
                ls1 += p01 + p81;
                *(__half2*)&pstage[il * 136 + cidx0] =
                    __halves2half2(__float2half_rn(p00), __float2half_rn(p01));
                *(__half2*)&pstage[(il + 8) * 136 + cidx0] =
                    __halves2half2(__float2half_rn(p80), __float2half_rn(p81));
            }
#pragma unroll
            for (int o = 4; o < 32; o <<= 1) {
                ls0 += __shfl_xor_sync(0xffffffffu, ls0, o);
                ls1 += __shfl_xor_sync(0xffffffffu, ls1, o);
            }
            if ((lane >> 2) == 0) {
                sSum[warpM * 128 + cidx0]     = ls0;
                sSum[warpM * 128 + cidx0 + 1] = ls1;
            }
        }
        __syncthreads();

        if (warpM == 0 && (lane >> 2) == 0) {
#pragma unroll
            for (int nt = 0; nt < 4; ++nt)
#pragma unroll
                for (int pp = 0; pp < 2; ++pp) {
                    const int cidx = warpN * 32 + nt * 8 + (lane & 3) * 2 + pp;
                    const float cmv = fmaxf(sMax[cidx], sMax[128 + cidx]);
                    const float tot = sSum[cidx] + sSum[128 + cidx];
                    const size_t o = ((size_t)b * 16 + blockIdx.y) * SS + n0 + cidx;
                    Pmax[o] = cmv;
                    Psum[o] = tot;
                }
        }

        __half* pB = Patt + (size_t)b * SS * SS;
#pragma unroll
        for (int u = 0; u < 8; ++u) {
            const int flat = u * 256 + t;
            const int r = flat >> 4, c16 = (flat & 15) * 8;
            uint4 val = *(uint4*)&pstage[r * 136 + c16];
            stcs_u4((uint4*)&pB[(size_t)(m0 + r) * SS + n0 + c16], val);
        }
    } else {
#pragma unroll
        for (int mt = 0; mt < 4; ++mt) {
            const size_t i = (size_t)m0 + warpM * 64 + mt * 16 + (lane >> 2);
#pragma unroll
            for (int nt = 0; nt < 4; ++nt) {
                const int n = n0 + warpN * 32 + nt * 8 + (lane & 3) * 2;
#pragma unroll
                for (int half = 0; half < 2; ++half) {
                    const size_t row = i + half * 8;
                    float x0 = acc[mt][nt][half * 2 + 0];
                    float x1 = acc[mt][nt][half * 2 + 1];
                    __half h0 = __float2half_rn(x0), h1 = __float2half_rn(x1);
                    __half l0 = __float2half_rn(x0 - __half2float(h0));
                    __half l1 = __float2half_rn(x1 - __half2float(h1));
                    *(__half2*)&Qhi[row * HH + n] = __halves2half2(h0, h1);
                    *(__half2*)&Qlo[row * HH + n] = __halves2half2(l0, l1);
                }
            }
        }
    }
}

// ===== combine per-tile partials into column stats (max, 1/sum) =============
__global__ __launch_bounds__(256) void combine_kernel(
    const float* __restrict__ Pmax, const float* __restrict__ Psum,
    float* __restrict__ cmax, float* __restrict__ rcs)
{
    const int idx = blockIdx.x * 256 + threadIdx.x;
    const int b = idx >> 11, j = idx & 2047;
    float pm[16];
#pragma unroll
    for (int tN = 0; tN < 16; ++tN)
        pm[tN] = Pmax[((size_t)b * 16 + tN) * SS + j];
    float m = pm[0];
#pragma unroll
    for (int tN = 1; tN < 16; ++tN) m = fmaxf(m, pm[tN]);
    float s = 0.f;
#pragma unroll
    for (int tN = 0; tN < 16; ++tN)
        s += Psum[((size_t)b * 16 + tN) * SS + j] * fexp(pm[tN] - m);
    cmax[idx] = m;
    rcs[idx]  = 1.0f / s;
}

// ===== attn = p*s (streaming scatter) + output = p @ (s*v) (2-term HMMA) =====
// 128-wide j-chunks, double-buffered p tiles. v via LDG (L2-hot).
#define FO_P     0                 // pS[2][128][136] halves (2 x 34816 B)
#define FO_PB    34816
#define FO_SVH   69632             // svHi [64][136] halves  (17408 B)
#define FO_SVL   87040             // svLo [64][136] halves  (17408 B)
#define FO_SC    104448            // scaleS [128] floats    (512 B)
#define FO_IDX   104960            // idxS   [128] ints      (512 B)
#define FO_TOTAL 105472
__global__ void __launch_bounds__(256, 2) fused_out_mma_kernel(
    const __half* __restrict__ patt, const float* __restrict__ vT,
    const float* __restrict__ pmax, const float* __restrict__ cmax,
    const float* __restrict__ rcs, const int* __restrict__ idx,
    const int* __restrict__ cnt, float* __restrict__ attOut,
    float* __restrict__ Out)
{
    extern __shared__ __half sm[];
    char* smc = (char*)sm;
    float* scaleS = (float*)(smc + FO_SC);
    int*   idxS   = (int*)(smc + FO_IDX);
    __half* svH   = (__half*)(smc + FO_SVH);
    __half* svL   = (__half*)(smc + FO_SVL);

    const int t    = threadIdx.x;
    const int lane = t & 31;
    const int wid  = t >> 5;
    const int warpM = wid >> 2;
    const int warpN = wid & 3;
    const int b    = blockIdx.y;
    const int tile = blockIdx.x;
    const int i0   = tile * 128;

    const int cntb = cnt[b];
    if (i0 >= cntb) return;

    if (t < 128) idxS[t] = idx[(size_t)b * SS + i0 + t];

    const __half* pB = patt + (size_t)b * SS * SS;
    float* aB = attOut + (size_t)b * SS * SS;
    const float* vB = vT + (size_t)b * ZZ * SS;

    const uint32_t smb = smem_u32(sm);

    float acc[4][2][4];
#pragma unroll
    for (int mt = 0; mt < 4; ++mt)
#pragma unroll
        for (int nt = 0; nt < 2; ++nt)
#pragma unroll
            for (int r = 0; r < 4; ++r) acc[mt][nt][r] = 0.f;

    const int aRow = warpM * 64 + (lane & 7) + ((lane >> 3) & 1) * 8;
    const int aK   = (lane >> 4) * 8;
    const int bRow = warpN * 16 + (lane & 7) + (lane >> 4) * 8;
    const int bK   = ((lane >> 3) & 1) * 8;

    auto issue_p = [&](int jt, int buf) {
        const int j0 = jt * 128;
#pragma unroll
        for (int u = 0; u < 8; ++u) {
            const int flat = u * 256 + t;
            const int pr = flat >> 4, pc = (flat & 15) * 8;
            const __half* gp = pB + (size_t)(i0 + pr) * SS + j0 + pc;
            const uint32_t dp = smb + (uint32_t)(FO_P + buf * FO_PB + (pr * 136 + pc) * 2);
            asm volatile("cp.async.cg.shared.global [%0], [%1], 16;" :: "r"(dp), "l"(gp));
        }
        asm volatile("cp.async.commit_group;" ::: "memory");
    };

    issue_p(0, 0);

    for (int jt = 0; jt < 16; ++jt) {
        const int j0 = jt * 128;
        const int buf = jt & 1;
        __half* pS = (__half*)(smc + FO_P + buf * FO_PB);

        asm volatile("cp.async.wait_group 0;" ::: "memory");
        __syncthreads();

        if (t < 128) {
            const int j = j0 + t;
            scaleS[t] = fexp(pmax[((size_t)b * 16 + tile) * SS + j]
                             - cmax[(size_t)b * SS + j]) * rcs[(size_t)b * SS + j];
        }

        if (jt + 1 < 16) issue_p(jt + 1, buf ^ 1);
        __syncthreads();

#pragma unroll
        for (int u = 0; u < 8; ++u) {
            const int flat = u * 256 + t;
            const int d = flat >> 5, j = (flat & 31) * 4;
            float4 vv = *(const float4*)&vB[(size_t)d * SS + j0 + j];
            float a0 = vv.x * scaleS[j + 0];
            float a1 = vv.y * scaleS[j + 1];
            float a2 = vv.z * scaleS[j + 2];
            float a3 = vv.w * scaleS[j + 3];
            __half h0 = __float2half_rn(a0), h1 = __float2half_rn(a1);
            __half h2 = __float2half_rn(a2), h3 = __float2half_rn(a3);
            __half l0 = __float2half_rn(a0 - __half2float(h0));
            __half l1 = __float2half_rn(a1 - __half2float(h1));
            __half l2 = __float2half_rn(a2 - __half2float(h2));
            __half l3 = __float2half_rn(a3 - __half2float(h3));
            __half2* ph = (__half2*)&svH[d * 136 + j];
            ph[0] = __halves2half2(h0, h1); ph[1] = __halves2half2(h2, h3);
            __half2* pl = (__half2*)&svL[d * 136 + j];
            pl[0] = __halves2half2(l0, l1); pl[1] = __halves2half2(l2, l3);
        }

#pragma unroll
        for (int u = 0; u < 8; ++u) {
            const int flat = u * 256 + t;
            const int r = flat >> 4, c = (flat & 15) * 8;
            if (i0 + r < cntb) {
                uint4 praw = *(uint4*)&pS[r * 136 + c];
                __half2 p01 = *(__half2*)&praw.x, p23 = *(__half2*)&praw.y;
                __half2 p45 = *(__half2*)&praw.z, p67 = *(__half2*)&praw.w;
                float2 f0 = __half22float2(p01), f1 = __half22float2(p23);
                float2 f2 = __half22float2(p45), f3 = __half22float2(p67);
                float4 w0, w1;
                w0.x = f0.x * scaleS[c + 0]; w0.y = f0.y * scaleS[c + 1];
                w0.z = f1.x * scaleS[c + 2]; w0.w = f1.y * scaleS[c + 3];
                w1.x = f2.x * scaleS[c + 4]; w1.y = f2.y * scaleS[c + 5];
                w1.z = f3.x * scaleS[c + 6]; w1.w = f3.y * scaleS[c + 7];
                float* dst = &aB[(size_t)idxS[r] * SS + j0 + c];
                stcs_f4((float4*)dst, w0);
                stcs_f4((float4*)(dst + 4), w1);
            }
        }
        __syncthreads();

        const uint32_t pSb = smb + (uint32_t)(FO_P + buf * FO_PB);
#pragma unroll
        for (int k16 = 0; k16 < 128; k16 += 16) {
            uint32_t ap[4][4], bh[4], bl[4];
#pragma unroll
            for (int mt = 0; mt < 4; ++mt) {
                const uint32_t adr = pSb +
                    (uint32_t)(((aRow + mt * 16) * 136 + k16 + aK) * 2);
                LDSM4(ap[mt], adr);
            }
            const uint32_t badr = smb +
                (uint32_t)(FO_SVH + (bRow * 136 + k16 + bK) * 2);
            LDSM4(bh, badr);
            LDSM4(bl, badr + (FO_SVL - FO_SVH));
#pragma unroll
            for (int mt = 0; mt < 4; ++mt)
#pragma unroll
                for (int nt = 0; nt < 2; ++nt) {
                    const uint32_t bhf[2] = { bh[nt * 2], bh[nt * 2 + 1] };
                    const uint32_t blf[2] = { bl[nt * 2], bl[nt * 2 + 1] };
                    hmma16816(acc[mt][nt], ap[mt], bhf);
                    hmma16816(acc[mt][nt], ap[mt], blf);
                }
        }
    }

#pragma unroll
    for (int mt = 0; mt < 4; ++mt) {
        const int ci = i0 + warpM * 64 + mt * 16 + (lane >> 2);
#pragma unroll
        for (int nt = 0; nt < 2; ++nt) {
            const int d = warpN * 16 + nt * 8 + (lane & 3) * 2;
            if (ci < cntb) {
                float2 v0; v0.x = acc[mt][nt][0]; v0.y = acc[mt][nt][1];
                *(float2*)&Out[((size_t)b * SS + idxS[ci - i0]) * ZZ + d] = v0;
            }
            if (ci + 8 < cntb) {
                float2 v8; v8.x = acc[mt][nt][2]; v8.y = acc[mt][nt][3];
                *(float2*)&Out[((size_t)b * SS + idxS[ci + 8 - i0]) * ZZ + d] = v8;
            }
        }
    }
}

// ============================== launch ======================================
extern "C" void kernel_launch(void* const* d_in, const int* in_sizes, int n_in,
                              void* d_out, int out_size)
{
    const float* enc  = (const float*)d_in[0];
    const float* dec  = (const float*)d_in[1];
    const float* lat  = (const float*)d_in[3];
    const void*  mask = d_in[4];
    const float* Wq   = (const float*)d_in[5];
    const float* Wk   = (const float*)d_in[6];
    const float* Wv   = (const float*)d_in[7];

    float* outp = (float*)d_out;

    const size_t OUTE = (size_t)BB * SS * ZZ;
    const size_t ATTE = (size_t)BB * SS * SS;

    float  *vtp, *cmaxp, *rcsp, *pmaxp, *psump, *attfb;
    __half *GThi, *GTlo, *dhi, *dlo, *ehi, *elo, *qhi, *qlo, *pattp;
    int *idxp, *cntp;
    cudaGetSymbolAddress((void**)&GThi,  g_GThi);
    cudaGetSymbolAddress((void**)&GTlo,  g_GTlo);
    cudaGetSymbolAddress((void**)&dhi,   g_dechi);
    cudaGetSymbolAddress((void**)&dlo,   g_declo);
    cudaGetSymbolAddress((void**)&ehi,   g_ehi);
    cudaGetSymbolAddress((void**)&elo,   g_elo);
    cudaGetSymbolAddress((void**)&qhi,   g_qhi);
    cudaGetSymbolAddress((void**)&qlo,   g_qlo);
    cudaGetSymbolAddress((void**)&vtp,   g_vT);
    cudaGetSymbolAddress((void**)&pattp, g_patt);
    cudaGetSymbolAddress((void**)&pmaxp, g_pmax);
    cudaGetSymbolAddress((void**)&psump, g_psum);
    cudaGetSymbolAddress((void**)&cmaxp, g_cmax);
    cudaGetSymbolAddress((void**)&rcsp,  g_rcs);
    cudaGetSymbolAddress((void**)&idxp,  g_idx);
    cudaGetSymbolAddress((void**)&cntp,  g_cnt);
    cudaGetSymbolAddress((void**)&attfb, g_att);

    float* attnbuf = ((size_t)out_size >= OUTE + ATTE) ? (outp + OUTE) : attfb;

    const int M = BB * SS;   // 65536

    static int inited = 0;
    static cudaStream_t s1, s2, s3;
    static cudaEvent_t evF, ev1, ev2, ev3;
    if (!inited) {
        cudaFuncSetAttribute(mma_split_kernel<true>,
                             cudaFuncAttributeMaxDynamicSharedMemorySize, 81920);
        cudaFuncSetAttribute(mma_split_kernel<false>,
                             cudaFuncAttributeMaxDynamicSharedMemorySize, 81920);
        cudaFuncSetAttribute(fused_out_mma_kernel,
                             cudaFuncAttributeMaxDynamicSharedMemorySize, FO_TOTAL);
        cudaStreamCreateWithFlags(&s1, cudaStreamNonBlocking);
        cudaStreamCreateWithFlags(&s2, cudaStreamNonBlocking);
        cudaStreamCreateWithFlags(&s3, cudaStreamNonBlocking);
        cudaEventCreateWithFlags(&evF, cudaEventDisableTiming);
        cudaEventCreateWithFlags(&ev1, cudaEventDisableTiming);
        cudaEventCreateWithFlags(&ev2, cudaEventDisableTiming);
        cudaEventCreateWithFlags(&ev3, cudaEventDisableTiming);
        inited = 1;
    }

    // ---- fork side streams off the main (capture) stream ----
    cudaEventRecord(evF, 0);
    cudaStreamWaitEvent(s1, evF, 0);
    cudaStreamWaitEvent(s2, evF, 0);
    cudaStreamWaitEvent(s3, evF, 0);

    // s1: GT = Wk @ Wq^T, split fp16  (needed by qproj)
    gmatsplit_kernel<<<dim3(4, 4), 256, 0, s1>>>(Wk, Wq, GThi, GTlo);
    cudaEventRecord(ev1, s1);

    // s2: enc split  (needed by align)
    split_kernel<<<592, 256, 0, s2>>>(enc, ehi, elo, M * HH / 4);
    cudaEventRecord(ev2, s2);

    // s3: vT + zerofill  (needed by fused_out)
    vprojtrans_kernel<<<M / 32, 256, 0, s3>>>(lat, Wv, vtp);
    zerofill_kernel<<<dim3(SS, BB), 256, 0, s3>>>(mask, attnbuf, outp);
    cudaEventRecord(ev3, s3);

    // ---- main stream: critical path ----
    compact_kernel<<<BB, 256>>>(mask, idxp, cntp);
    gsplit_kernel<<<M / 4, 256>>>(dec, idxp, cntp, dhi, dlo);

    cudaStreamWaitEvent(0, ev1, 0);
    // q' = compacted dec @ GT^T
    mma_split_kernel<false><<<dim3(HH / 128, M / 128, 1), 256, 81920>>>(
        dhi, dlo, GThi, GTlo, cntp, nullptr, qhi, qlo, nullptr, nullptr);

    cudaStreamWaitEvent(0, ev2, 0);
    // p = exp(masked-scaled logits - tilemax), compact rows only
    mma_split_kernel<true><<<dim3(SS / 128, SS / 128, BB), 256, 81920>>>(
        qhi, qlo, ehi, elo, cntp, pattp, nullptr, nullptr, pmaxp, psump);

    combine_kernel<<<(BB * SS) / 256, 256>>>(pmaxp, psump, cmaxp, rcsp);

    cudaStreamWaitEvent(0, ev3, 0);
    fused_out_mma_kernel<<<dim3(SS / 128, BB), 256, FO_TOTAL>>>(
        pattp, vtp, pmaxp, cmaxp, rcsp, idxp, cntp, attnbuf, outp);
}

// round 16
// speedup vs baseline: 1.0258x; 1.0258x over previous
#include <cuda_runtime.h>
#include <cuda_fp16.h>
#include <cstdint>
#include <cstddef>

// Problem sizes (fixed)
#define BB 32
#define SS 2048
#define HH 256
#define ZZ 64

#define INV_T   (0.0625f)   // 1/sqrt(256)
#define NEGINF  (-1e9f)

// ---------------- scratch (device globals; no allocations allowed) ----------
__device__ __half g_GThi[HH * HH];
__device__ __half g_GTlo[HH * HH];
__device__ __half g_ehi[(size_t)BB * SS * HH];
__device__ __half g_elo[(size_t)BB * SS * HH];
__device__ __half g_qhi[(size_t)BB * SS * HH];     // q' compact
__device__ __half g_qlo[(size_t)BB * SS * HH];
__device__ float  g_vT[(size_t)BB * ZZ * SS];      // v^T fp32, [b][d][s]
__device__ __half g_patt[(size_t)BB * SS * SS];    // p compact rows, fp16
__device__ float  g_pmax[(size_t)BB * 16 * SS];
__device__ float  g_psum[(size_t)BB * 16 * SS];
__device__ float  g_cmax[(size_t)BB * SS];
__device__ float  g_rcs[(size_t)BB * SS];
__device__ int    g_idx[(size_t)BB * SS];          // unmasked row indices
__device__ int    g_cnt[BB];
__device__ float  g_att[(size_t)BB * SS * SS];     // fallback attn buffer

// ---------------- mask dtype detection --------------------------------------
__device__ __forceinline__ bool mask_is_i32(const void* m) {
    const unsigned int* p = (const unsigned int*)m;
    unsigned int o = p[0] | p[1] | p[2] | p[3] | p[4] | p[5] | p[6] | p[7];
    return o <= 1u;
}

__device__ __forceinline__ uint32_t smem_u32(const void* p) {
    uint32_t a;
    asm("{ .reg .u64 t; cvta.to.shared.u64 t, %1; cvt.u32.u64 %0, t; }" : "=r"(a) : "l"(p));
    return a;
}

// FMA-pipe exp (no MUFU)
__device__ __forceinline__ float fexp(float x) {
    float y = fmaxf(x * 1.4426950408889634f, -126.0f);
    float r = rintf(y);
    float f = y - r;
    float p =              1.3333558146e-3f;
    p = fmaf(p, f, 9.6181291077e-3f);
    p = fmaf(p, f, 5.5504108664e-2f);
    p = fmaf(p, f, 2.4022650696e-1f);
    p = fmaf(p, f, 6.9314718056e-1f);
    p = fmaf(p, f, 1.0f);
    return __int_as_float(__float_as_int(p) + (((int)r) << 23));
}

__device__ __forceinline__ void hmma16816(float* d, const uint32_t* a, const uint32_t* b) {
    asm volatile(
        "mma.sync.aligned.m16n8k16.row.col.f32.f16.f16.f32 "
        "{%0,%1,%2,%3}, {%4,%5,%6,%7}, {%8,%9}, {%0,%1,%2,%3};"
        : "+f"(d[0]), "+f"(d[1]), "+f"(d[2]), "+f"(d[3])
        : "r"(a[0]), "r"(a[1]), "r"(a[2]), "r"(a[3]), "r"(b[0]), "r"(b[1]));
}

#define LDSM4(r, a) \
    asm volatile("ldmatrix.sync.aligned.m8n8.x4.shared.b16 {%0,%1,%2,%3}, [%4];" \
        : "=r"((r)[0]), "=r"((r)[1]), "=r"((r)[2]), "=r"((r)[3]) : "r"(a))

// ========== compact: per-batch list of unmasked row indices ==================
__global__ __launch_bounds__(256) void compact_kernel(
    const void* __restrict__ mask, int* __restrict__ idx, int* __restrict__ cnt)
{
    const int b = blockIdx.x;
    const int t = threadIdx.x;
    const bool i32 = mask_is_i32(mask);
    const int*           mi = (const int*)mask;
    const unsigned char* mb = (const unsigned char*)mask;

    int loc[8]; int c = 0;
#pragma unroll
    for (int k = 0; k < 8; ++k) {
        const int i = t * 8 + k;
        const int v = i32 ? (mi[b * SS + i] != 0) : (mb[b * SS + i] != 0);
        loc[k] = v; c += v;
    }
    __shared__ int ps[256];
    ps[t] = c;
    __syncthreads();
    for (int off = 1; off < 256; off <<= 1) {
        int v = (t >= off) ? ps[t - off] : 0;
        __syncthreads();
        ps[t] += v;
        __syncthreads();
    }
    int base = ps[t] - c;
#pragma unroll
    for (int k = 0; k < 8; ++k)
        if (loc[k]) idx[(size_t)b * SS + (base++)] = t * 8 + k;
    const int total = ps[255];
    __syncthreads();
    for (int p = total + t; p < SS; p += 256) idx[(size_t)b * SS + p] = 0;
    if (t == 0) cnt[b] = total;
}

// ========== zero-fill masked attn rows + output rows =========================
__global__ __launch_bounds__(256) void zerofill_kernel(
    const void* __restrict__ mask, float* __restrict__ att, float* __restrict__ Out)
{
    const int b = blockIdx.y, i = blockIdx.x, t = threadIdx.x;
    const bool i32 = mask_is_i32(mask);
    const bool keep = i32 ? (((const int*)mask)[b * SS + i] != 0)
                          : (((const unsigned char*)mask)[b * SS + i] != 0);
    if (keep) return;
    const float4 z = make_float4(0.f, 0.f, 0.f, 0.f);
    float* row = att + ((size_t)b * SS + i) * SS;
#pragma unroll
    for (int u = 0; u < 2; ++u)
        *(float4*)&row[(u * 256 + t) * 4] = z;
    if (t < 16)
        *(float4*)&Out[((size_t)b * SS + i) * ZZ + t * 4] = z;
}

// ====== gmat+split: GT = Wk @ Wq^T (256x256x256), written as fp16 hi/lo ======
__global__ __launch_bounds__(256) void gmatsplit_kernel(
    const float* __restrict__ A, const float* __restrict__ B,
    __half* __restrict__ Ohi, __half* __restrict__ Olo)
{
    __shared__ float aS[32 * 65];
    __shared__ float bS[32 * 65];
    const int t  = threadIdx.x;
    const int r0 = blockIdx.y * 64;
    const int c0 = blockIdx.x * 64;

    const int lr = t >> 2;
    const int lc = (t & 3) * 8;

    float acc[4][4];
#pragma unroll
    for (int u = 0; u < 4; ++u)
#pragma unroll
        for (int v = 0; v < 4; ++v) acc[u][v] = 0.f;

    for (int k0 = 0; k0 < HH; k0 += 32) {
        __syncthreads();
        float4 a0 = *(const float4*)&A[(size_t)(r0 + lr) * HH + k0 + lc];
        float4 a1 = *(const float4*)&A[(size_t)(r0 + lr) * HH + k0 + lc + 4];
        float4 b0 = *(const float4*)&B[(size_t)(c0 + lr) * HH + k0 + lc];
        float4 b1 = *(const float4*)&B[(size_t)(c0 + lr) * HH + k0 + lc + 4];
        aS[(lc + 0) * 65 + lr] = a0.x; aS[(lc + 1) * 65 + lr] = a0.y;
        aS[(lc + 2) * 65 + lr] = a0.z; aS[(lc + 3) * 65 + lr] = a0.w;
        aS[(lc + 4) * 65 + lr] = a1.x; aS[(lc + 5) * 65 + lr] = a1.y;
        aS[(lc + 6) * 65 + lr] = a1.z; aS[(lc + 7) * 65 + lr] = a1.w;
        bS[(lc + 0) * 65 + lr] = b0.x; bS[(lc + 1) * 65 + lr] = b0.y;
        bS[(lc + 2) * 65 + lr] = b0.z; bS[(lc + 3) * 65 + lr] = b0.w;
        bS[(lc + 4) * 65 + lr] = b1.x; bS[(lc + 5) * 65 + lr] = b1.y;
        bS[(lc + 6) * 65 + lr] = b1.z; bS[(lc + 7) * 65 + lr] = b1.w;
        __syncthreads();

        const int ty = t >> 4, tx = t & 15;
#pragma unroll
        for (int kk = 0; kk < 32; ++kk) {
            float a[4], bb[4];
#pragma unroll
            for (int u = 0; u < 4; ++u) { a[u] = aS[kk * 65 + ty * 4 + u]; bb[u] = bS[kk * 65 + tx * 4 + u]; }
#pragma unroll
            for (int u = 0; u < 4; ++u)
#pragma unroll
                for (int v = 0; v < 4; ++v) acc[u][v] += a[u] * bb[v];
        }
    }

    const int ty = t >> 4, tx = t & 15;
#pragma unroll
    for (int u = 0; u < 4; ++u) {
        const size_t o = (size_t)(r0 + ty * 4 + u) * HH + c0 + tx * 4;
        __half h[4], l[4];
#pragma unroll
        for (int v = 0; v < 4; ++v) {
            h[v] = __float2half_rn(acc[u][v]);
            l[v] = __float2half_rn(acc[u][v] - __half2float(h[v]));
        }
        *(__half2*)&Ohi[o]     = __halves2half2(h[0], h[1]);
        *(__half2*)&Ohi[o + 2] = __halves2half2(h[2], h[3]);
        *(__half2*)&Olo[o]     = __halves2half2(l[0], l[1]);
        *(__half2*)&Olo[o + 2] = __halves2half2(l[2], l[3]);
    }
}

// ============ split fp32 -> fp16 hi + fp16 lo (elementwise) ==================
__global__ __launch_bounds__(256) void split_kernel(
    const float* __restrict__ in, __half* __restrict__ hi, __half* __restrict__ lo, int n4)
{
    int i = blockIdx.x * 256 + threadIdx.x;
    int stride = gridDim.x * 256;
    for (; i < n4; i += stride) {
        float4 x = ((const float4*)in)[i];
        __half hx = __float2half_rn(x.x), hy = __float2half_rn(x.y);
        __half hz = __float2half_rn(x.z), hw = __float2half_rn(x.w);
        __half lx = __float2half_rn(x.x - __half2float(hx));
        __half ly = __float2half_rn(x.y - __half2float(hy));
        __half lz = __float2half_rn(x.z - __half2float(hz));
        __half lw = __float2half_rn(x.w - __half2float(hw));
        ((__half2*)hi)[i * 2 + 0] = __halves2half2(hx, hy);
        ((__half2*)hi)[i * 2 + 1] = __halves2half2(hz, hw);
        ((__half2*)lo)[i * 2 + 0] = __halves2half2(lx, ly);
        ((__half2*)lo)[i * 2 + 1] = __halves2half2(lz, lw);
    }
}

// ========== v = latent @ Wv, written directly transposed: vT[b][d][s] ========
__global__ __launch_bounds__(256) void vprojtrans_kernel(
    const float* __restrict__ X, const float* __restrict__ Wv, float* __restrict__ vT)
{
    __shared__ float Ws[64 * 65];
    __shared__ float Xs[32 * 65];
    __shared__ float sT[32 * 65];
    const int t  = threadIdx.x;
    const int b  = blockIdx.x >> 6;
    const int s0 = (blockIdx.x & 63) * 32;
    const size_t r0 = (size_t)b * SS + s0;

#pragma unroll
    for (int u = 0; u < 16; ++u) {
        int idx = u * 256 + t; int r = idx >> 6, c = idx & 63;
        Ws[r * 65 + c] = Wv[idx];
    }
#pragma unroll
    for (int u = 0; u < 8; ++u) {
        int idx = u * 256 + t; int r = idx >> 6, c = idx & 63;
        Xs[r * 65 + c] = X[(r0 + r) * 64 + c];
    }
    __syncthreads();

    const int row = t >> 3;
    const int c0  = (t & 7) * 8;
    float acc[8];
#pragma unroll
    for (int u = 0; u < 8; ++u) acc[u] = 0.f;
#pragma unroll 8
    for (int z = 0; z < 64; ++z) {
        float a = Xs[row * 65 + z];
#pragma unroll
        for (int u = 0; u < 8; ++u) acc[u] += a * Ws[z * 65 + c0 + u];
    }
#pragma unroll
    for (int u = 0; u < 8; ++u) sT[row * 65 + c0 + u] = acc[u];
    __syncthreads();

    const int d  = t >> 2;
    const int sc = (t & 3) * 8;
    float o[8];
#pragma unroll
    for (int k = 0; k < 8; ++k) o[k] = sT[(sc + k) * 65 + d];
    float4 w0, w1;
    w0.x = o[0]; w0.y = o[1]; w0.z = o[2]; w0.w = o[3];
    w1.x = o[4]; w1.y = o[5]; w1.z = o[6]; w1.w = o[7];
    float* dst = &vT[((size_t)b * ZZ + d) * SS + s0 + sc];
    *(float4*)dst       = w0;
    *(float4*)(dst + 4) = w1;
}

// ====== qproj: q' = gathered dec rows @ GT^T (fused gather+split+HMMA) =======
// A loaded as gathered fp32 dec rows (via idx), split to fp16 hi/lo in smem.
// smem bytes: Af32[2][128][36]f @0 (2x18432), B hi/lo [2][2][128][40]h @36864
// (2x20480), Ahi @77824 (10240), Alo @88064 (10240). Total 98304.
__global__ void __launch_bounds__(256, 2) qproj_kernel(
    const float* __restrict__ dec, const int* __restrict__ idx,
    const int* __restrict__ cnt,
    const __half* __restrict__ GThi, const __half* __restrict__ GTlo,
    __half* __restrict__ Qhi, __half* __restrict__ Qlo)
{
    extern __shared__ __half sm[];
    char* smc = (char*)sm;
    __shared__ int idxS[128];

    const int t    = threadIdx.x;
    const int lane = t & 31;
    const int wid  = t >> 5;
    const int warpM = wid >> 2;
    const int warpN = wid & 3;
    const int m0 = blockIdx.y * 128;      // flat compact row base
    const int n0 = blockIdx.x * 128;      // q' column base
    const int b  = m0 >> 11;
    const int cntb = cnt[b];
    if ((m0 & 2047) >= cntb) return;

    if (t < 128) idxS[t] = idx[(size_t)b * SS + (m0 & 2047) + t];
    __syncthreads();

    const uint32_t smb = smem_u32(sm);
    __half* Ahi = (__half*)(smc + 77824);
    __half* Alo = (__half*)(smc + 88064);

    float acc[4][4][4];
#pragma unroll
    for (int mt = 0; mt < 4; ++mt)
#pragma unroll
        for (int nt = 0; nt < 4; ++nt)
#pragma unroll
            for (int r = 0; r < 4; ++r) acc[mt][nt][r] = 0.f;

    auto issue = [&](int chunk, int p) {
        // A: gathered fp32 dec rows (128 x 32 floats)
#pragma unroll
        for (int u = 0; u < 4; ++u) {
            const int flat = u * 256 + t;
            const int r = flat >> 3;
            const int cc = (flat & 7) * 4;
            const float* g = dec + ((size_t)b * SS + idxS[r]) * HH + chunk * 32 + cc;
            const uint32_t d = smb + (uint32_t)(p * 18432 + (r * 36 + cc) * 4);
            asm volatile("cp.async.cg.shared.global [%0], [%1], 16;" :: "r"(d), "l"(g));
        }
        // B: GThi/GTlo (128 x 32 halves each)
#pragma unroll
        for (int u = 0; u < 4; ++u) {
            const int flat = u * 256 + t;
            const int tile = flat >> 9;
            const int w = flat & 511;
            const int r = w >> 2, c16 = (w & 3) * 8;
            const __half* g = (tile ? GTlo : GThi) + (size_t)(n0 + r) * HH + chunk * 32 + c16;
            const uint32_t d = smb +
                (uint32_t)(36864 + p * 20480 + tile * 10240 + (r * 40 + c16) * 2);
            asm volatile("cp.async.cg.shared.global [%0], [%1], 16;" :: "r"(d), "l"(g));
        }
        asm volatile("cp.async.commit_group;" ::: "memory");
    };

    issue(0, 0);

    const int aRow = warpM * 64 + (lane & 7) + ((lane >> 3) & 1) * 8;
    const int aK   = (lane >> 4) * 8;
    const int bRow = warpN * 32 + (lane & 7) + (lane >> 4) * 8;
    const int bK   = ((lane >> 3) & 1) * 8;

    for (int c = 0; c < 8; ++c) {
        asm volatile("cp.async.wait_group 0;" ::: "memory");
        __syncthreads();
        if (c < 7) issue(c + 1, (c + 1) & 1);

        const int p = c & 1;
        const float* Af = (const float*)(smc + p * 18432);

        // split A fp32 -> Ahi/Alo (4096 elems, 16/thread, conflict-free)
#pragma unroll
        for (int u = 0; u < 16; ++u) {
            const int e = u * 256 + t;
            const int r = e >> 5, cc = e & 31;
            float x = Af[r * 36 + cc];
            __half h = __float2half_rn(x);
            __half l = __float2half_rn(x - __half2float(h));
            Ahi[r * 40 + cc] = h;
            Alo[r * 40 + cc] = l;
        }
        __syncthreads();

        const uint32_t abase = smb + 77824;
        const uint32_t bbase = smb + (uint32_t)(36864 + p * 20480);

#pragma unroll
        for (int k16 = 0; k16 < 32; k16 += 16) {
            uint32_t ah[4][4], al[4][4], bh[2][4], bl[2][4];
#pragma unroll
            for (int mt = 0; mt < 4; ++mt) {
                const uint32_t adr = abase +
                    (uint32_t)(((aRow + mt * 16) * 40 + k16 + aK) * 2);
                LDSM4(ah[mt], adr);
                LDSM4(al[mt], adr + 10240);
            }
#pragma unroll
            for (int ntp = 0; ntp < 2; ++ntp) {
                const uint32_t adr = bbase +
                    (uint32_t)(((bRow + ntp * 16) * 40 + k16 + bK) * 2);
                LDSM4(bh[ntp], adr);
                LDSM4(bl[ntp], adr + 10240);
            }
#pragma unroll
            for (int mt = 0; mt < 4; ++mt)
#pragma unroll
                for (int nt = 0; nt < 4; ++nt) {
                    const uint32_t bhf[2] = { bh[nt >> 1][(nt & 1) * 2],
                                              bh[nt >> 1][(nt & 1) * 2 + 1] };
                    const uint32_t blf[2] = { bl[nt >> 1][(nt & 1) * 2],
                                              bl[nt >> 1][(nt & 1) * 2 + 1] };
                    hmma16816(acc[mt][nt], ah[mt], bhf);
                    hmma16816(acc[mt][nt], ah[mt], blf);
                    hmma16816(acc[mt][nt], al[mt], bhf);
                }
        }
    }

    // epilogue: write q' split fp16
#pragma unroll
    for (int mt = 0; mt < 4; ++mt) {
        const size_t i = (size_t)m0 + warpM * 64 + mt * 16 + (lane >> 2);
#pragma unroll
        for (int nt = 0; nt < 4; ++nt) {
            const int n = n0 + warpN * 32 + nt * 8 + (lane & 3) * 2;
#pragma unroll
            for (int half = 0; half < 2; ++half) {
                const size_t row = i + half * 8;
                float x0 = acc[mt][nt][half * 2 + 0];
                float x1 = acc[mt][nt][half * 2 + 1];
                __half h0 = __float2half_rn(x0), h1 = __float2half_rn(x1);
                __half l0 = __float2half_rn(x0 - __half2float(h0));
                __half l1 = __float2half_rn(x1 - __half2float(h1));
                *(__half2*)&Qhi[row * HH + n] = __halves2half2(h0, h1);
                *(__half2*)&Qlo[row * HH + n] = __halves2half2(l0, l1);
            }
        }
    }
}

// =========== align: p = exp((q'@enc^T)/T - tilemax), 3-term HMMA =============
// CTA tile 128x128, 8 warps (2x4), warp tile 64x32, k-chunk 32, double buffer.
// Rows are COMPACTED (unmasked only); tiles past cnt early-exit.
__global__ void __launch_bounds__(256, 2) align_mma_kernel(
    const __half* __restrict__ Ahig, const __half* __restrict__ Alog,
    const __half* __restrict__ Bhig, const __half* __restrict__ Blog,
    const int* __restrict__ cnt, __half* __restrict__ Patt,
    float* __restrict__ Pmax, float* __restrict__ Psum)
{
    extern __shared__ __half sm[];
    const int t    = threadIdx.x;
    const int lane = t & 31;
    const int wid  = t >> 5;
    const int warpM = wid >> 2;
    const int warpN = wid & 3;
    const int b  = blockIdx.z;
    const int m0 = blockIdx.y * 128;
    const int n0 = blockIdx.x * 128;

    const int cntb = cnt[b];
    if (m0 >= cntb) {
        if (t < 128) {
            const size_t o = ((size_t)b * 16 + blockIdx.y) * SS + n0 + t;
            Pmax[o] = -1e30f;
            Psum[o] = 0.f;
        }
        return;
    }

    const size_t arow = (size_t)b * SS + m0;
    const size_t brow = (size_t)b * SS + n0;
    const __half* Ah = Ahig + arow * HH;
    const __half* Al = Alog + arow * HH;
    const __half* Bh = Bhig + brow * HH;
    const __half* Bl = Blog + brow * HH;

    const uint32_t smbase = smem_u32(sm);

    float acc[4][4][4];
#pragma unroll
    for (int mt = 0; mt < 4; ++mt)
#pragma unroll
        for (int nt = 0; nt < 4; ++nt)
#pragma unroll
            for (int r = 0; r < 4; ++r) acc[mt][nt][r] = 0.f;

    auto issue = [&](int chunk, int p) {
#pragma unroll
        for (int i = 0; i < 8; ++i) {
            const __half* basep = (i < 2) ? Ah : (i < 4) ? Al : (i < 6) ? Bh : Bl;
            const int tile = i >> 1;
            const int flat = i * 256 + t;
            const int w = flat & 511;
            const int r = w >> 2, c16 = w & 3;
            const __half* g = basep + (size_t)r * HH + chunk * 32 + c16 * 8;
            const uint32_t d = smbase +
                (uint32_t)((p * 20480 + tile * 5120 + r * 40 + c16 * 8) * 2);
            asm volatile("cp.async.cg.shared.global [%0], [%1], 16;" :: "r"(d), "l"(g));
        }
        asm volatile("cp.async.commit_group;" ::: "memory");
    };

    issue(0, 0);

    const int aRow = warpM * 64 + (lane & 7) + ((lane >> 3) & 1) * 8;
    const int aK   = (lane >> 4) * 8;
    const int bRow = warpN * 32 + (lane & 7) + (lane >> 4) * 8;
    const int bK   = ((lane >> 3) & 1) * 8;

    for (int c = 0; c < 8; ++c) {
        asm volatile("cp.async.wait_group 0;" ::: "memory");
        __syncthreads();
        if (c < 7) issue(c + 1, (c + 1) & 1);

        const int p = c & 1;
        const uint32_t abase = smbase + (uint32_t)(p * 20480 * 2);
        const uint32_t bbase = abase + 10240 * 2;

#pragma unroll
        for (int k16 = 0; k16 < 32; k16 += 16) {
            uint32_t ah[4][4], al[4][4], bh[2][4], bl[2][4];
#pragma unroll
            for (int mt = 0; mt < 4; ++mt) {
                const uint32_t adr = abase +
                    (uint32_t)(((aRow + mt * 16) * 40 + k16 + aK) * 2);
                LDSM4(ah[mt], adr);
                LDSM4(al[mt], adr + 10240);
            }
#pragma unroll
            for (int ntp = 0; ntp < 2; ++ntp) {
                const uint32_t adr = bbase +
                    (uint32_t)(((bRow + ntp * 16) * 40 + k16 + bK) * 2);
                LDSM4(bh[ntp], adr);
                LDSM4(bl[ntp], adr + 10240);
            }
#pragma unroll
            for (int mt = 0; mt < 4; ++mt)
#pragma unroll
                for (int nt = 0; nt < 4; ++nt) {
                    const uint32_t bhf[2] = { bh[nt >> 1][(nt & 1) * 2],
                                              bh[nt >> 1][(nt & 1) * 2 + 1] };
                    const uint32_t blf[2] = { bl[nt >> 1][(nt & 1) * 2],
                                              bl[nt >> 1][(nt & 1) * 2 + 1] };
                    hmma16816(acc[mt][nt], ah[mt], bhf);
                    hmma16816(acc[mt][nt], ah[mt], blf);
                    hmma16816(acc[mt][nt], al[mt], bhf);
                }
        }
    }

    // ----------------------------- epilogue ---------------------------------
#pragma unroll
    for (int mt = 0; mt < 4; ++mt) {
        const int ci = m0 + warpM * 64 + mt * 16 + (lane >> 2);
        const bool k0 = ci < cntb;
        const bool k8 = (ci + 8) < cntb;
#pragma unroll
        for (int nt = 0; nt < 4; ++nt) {
            acc[mt][nt][0] = k0 ? acc[mt][nt][0] * INV_T : NEGINF;
            acc[mt][nt][1] = k0 ? acc[mt][nt][1] * INV_T : NEGINF;
            acc[mt][nt][2] = k8 ? acc[mt][nt][2] * INV_T : NEGINF;
            acc[mt][nt][3] = k8 ? acc[mt][nt][3] * INV_T : NEGINF;
        }
    }

    __half* pstage = sm;                        // [128][136] halves
    float*  sMax   = (float*)(sm + 17408);      // [2][128]
    float*  sSum   = sMax + 256;                // [2][128]
    __syncthreads();

#pragma unroll
    for (int nt = 0; nt < 4; ++nt)
#pragma unroll
        for (int pp = 0; pp < 2; ++pp) {
            float lm = -3.4e38f;
#pragma unroll
            for (int mt = 0; mt < 4; ++mt) {
                lm = fmaxf(lm, acc[mt][nt][pp]);
                lm = fmaxf(lm, acc[mt][nt][2 + pp]);
            }
#pragma unroll
            for (int o = 4; o < 32; o <<= 1)
                lm = fmaxf(lm, __shfl_xor_sync(0xffffffffu, lm, o));
            const int cidx = warpN * 32 + nt * 8 + (lane & 3) * 2 + pp;
            if ((lane >> 2) == 0) sMax[warpM * 128 + cidx] = lm;
        }
    __syncthreads();

#pragma unroll
    for (int nt = 0; nt < 4; ++nt) {
        const int cidx0 = warpN * 32 + nt * 8 + (lane & 3) * 2;
        const float cmv0 = fmaxf(sMax[cidx0],     sMax[128 + cidx0]);
        const float cmv1 = fmaxf(sMax[cidx0 + 1], sMax[128 + cidx0 + 1]);
        float ls0 = 0.f, ls1 = 0.f;
#pragma unroll
        for (int mt = 0; mt < 4; ++mt) {
            const int il = warpM * 64 + mt * 16 + (lane >> 2);
            float p00 = fexp(acc[mt][nt][0] - cmv0);
            float p01 = fexp(acc[mt][nt][1] - cmv1);
            float p80 = fexp(acc[mt][nt][2] - cmv0);
            float p81 = fexp(acc[mt][nt][3] - cmv1);
            ls0 += p00 + p80;
            ls1 += p01 + p81;
            *(__half2*)&pstage[il * 136 + cidx0] =
                __halves2half2(__float2half_rn(p00), __float2half_rn(p01));
            *(__half2*)&pstage[(il + 8) * 136 + cidx0] =
                __halves2half2(__float2half_rn(p80), __float2half_rn(p81));
        }
#pragma unroll
        for (int o = 4; o < 32; o <<= 1) {
            ls0 += __shfl_xor_sync(0xffffffffu, ls0, o);
            ls1 += __shfl_xor_sync(0xffffffffu, ls1, o);
        }
        if ((lane >> 2) == 0) {
            sSum[warpM * 128 + cidx0]     = ls0;
            sSum[warpM * 128 + cidx0 + 1] = ls1;
        }
    }
    __syncthreads();

    if (warpM == 0 && (lane >> 2) == 0) {
#pragma unroll
        for (int nt = 0; nt < 4; ++nt)
#pragma unroll
            for (int pp = 0; pp < 2; ++pp) {
                const int cidx = warpN * 32 + nt * 8 + (lane & 3) * 2 + pp;
                const float cmv = fmaxf(sMax[cidx], sMax[128 + cidx]);
                const float tot = sSum[cidx] + sSum[128 + cidx];
                const size_t o = ((size_t)b * 16 + blockIdx.y) * SS + n0 + cidx;
                Pmax[o] = cmv;
                Psum[o] = tot;
            }
    }

    __half* pB = Patt + (size_t)b * SS * SS;
#pragma unroll
    for (int u = 0; u < 8; ++u) {
        const int flat = u * 256 + t;
        const int r = flat >> 4, c16 = (flat & 15) * 8;
        uint4 val = *(uint4*)&pstage[r * 136 + c16];
        *(uint4*)&pB[(size_t)(m0 + r) * SS + n0 + c16] = val;
    }
}

// ===== combine per-tile partials into column stats (max, 1/sum) =============
__global__ __launch_bounds__(256) void combine_kernel(
    const float* __restrict__ Pmax, const float* __restrict__ Psum,
    float* __restrict__ cmax, float* __restrict__ rcs)
{
    const int idx = blockIdx.x * 256 + threadIdx.x;
    const int b = idx >> 11, j = idx & 2047;
    float pm[16];
#pragma unroll
    for (int tN = 0; tN < 16; ++tN)
        pm[tN] = Pmax[((size_t)b * 16 + tN) * SS + j];
    float m = pm[0];
#pragma unroll
    for (int tN = 1; tN < 16; ++tN) m = fmaxf(m, pm[tN]);
    float s = 0.f;
#pragma unroll
    for (int tN = 0; tN < 16; ++tN)
        s += Psum[((size_t)b * 16 + tN) * SS + j] * fexp(pm[tN] - m);
    cmax[idx] = m;
    rcs[idx]  = 1.0f / s;
}

// ===== attn = p*s (scatter fp32) + output = p @ (s*v) (2-term HMMA) ==========
// 128-wide j-chunks, double-buffered p tiles. v via LDG (L2-hot).
#define FO_P     0                 // pS[2][128][136] halves (2 x 34816 B)
#define FO_PB    34816
#define FO_SVH   69632             // svHi [64][136] halves  (17408 B)
#define FO_SVL   87040             // svLo [64][136] halves  (17408 B)
#define FO_SC    104448            // scaleS [128] floats    (512 B)
#define FO_IDX   104960            // idxS   [128] ints      (512 B)
#define FO_TOTAL 105472
__global__ void __launch_bounds__(256, 2) fused_out_mma_kernel(
    const __half* __restrict__ patt, const float* __restrict__ vT,
    const float* __restrict__ pmax, const float* __restrict__ cmax,
    const float* __restrict__ rcs, const int* __restrict__ idx,
    const int* __restrict__ cnt, float* __restrict__ attOut,
    float* __restrict__ Out)
{
    extern __shared__ __half sm[];
    char* smc = (char*)sm;
    float* scaleS = (float*)(smc + FO_SC);
    int*   idxS   = (int*)(smc + FO_IDX);
    __half* svH   = (__half*)(smc + FO_SVH);
    __half* svL   = (__half*)(smc + FO_SVL);

    const int t    = threadIdx.x;
    const int lane = t & 31;
    const int wid  = t >> 5;
    const int warpM = wid >> 2;
    const int warpN = wid & 3;
    const int b    = blockIdx.y;
    const int tile = blockIdx.x;
    const int i0   = tile * 128;

    const int cntb = cnt[b];
    if (i0 >= cntb) return;

    if (t < 128) idxS[t] = idx[(size_t)b * SS + i0 + t];

    const __half* pB = patt + (size_t)b * SS * SS;
    float* aB = attOut + (size_t)b * SS * SS;
    const float* vB = vT + (size_t)b * ZZ * SS;

    const uint32_t smb = smem_u32(sm);

    float acc[4][2][4];
#pragma unroll
    for (int mt = 0; mt < 4; ++mt)
#pragma unroll
        for (int nt = 0; nt < 2; ++nt)
#pragma unroll
            for (int r = 0; r < 4; ++r) acc[mt][nt][r] = 0.f;

    const int aRow = warpM * 64 + (lane & 7) + ((lane >> 3) & 1) * 8;
    const int aK   = (lane >> 4) * 8;
    const int bRow = warpN * 16 + (lane & 7) + (lane >> 4) * 8;
    const int bK   = ((lane >> 3) & 1) * 8;

    auto issue_p = [&](int jt, int buf) {
        const int j0 = jt * 128;
#pragma unroll
        for (int u = 0; u < 8; ++u) {
            const int flat = u * 256 + t;
            const int pr = flat >> 4, pc = (flat & 15) * 8;
            const __half* gp = pB + (size_t)(i0 + pr) * SS + j0 + pc;
            const uint32_t dp = smb + (uint32_t)(FO_P + buf * FO_PB + (pr * 136 + pc) * 2);
            asm volatile("cp.async.cg.shared.global [%0], [%1], 16;" :: "r"(dp), "l"(gp));
        }
        asm volatile("cp.async.commit_group;" ::: "memory");
    };

    issue_p(0, 0);

    for (int jt = 0; jt < 16; ++jt) {
        const int j0 = jt * 128;
        const int buf = jt & 1;
        __half* pS = (__half*)(smc + FO_P + buf * FO_PB);

        asm volatile("cp.async.wait_group 0;" ::: "memory");
        __syncthreads();

        if (t < 128) {
            const int j = j0 + t;
            scaleS[t] = fexp(pmax[((size_t)b * 16 + tile) * SS + j]
                             - cmax[(size_t)b * SS + j]) * rcs[(size_t)b * SS + j];
        }

        if (jt + 1 < 16) issue_p(jt + 1, buf ^ 1);
        __syncthreads();

#pragma unroll
        for (int u = 0; u < 8; ++u) {
            const int flat = u * 256 + t;
            const int d = flat >> 5, j = (flat & 31) * 4;
            float4 vv = *(const float4*)&vB[(size_t)d * SS + j0 + j];
            float a0 = vv.x * scaleS[j + 0];
            float a1 = vv.y * scaleS[j + 1];
            float a2 = vv.z * scaleS[j + 2];
            float a3 = vv.w * scaleS[j + 3];
            __half h0 = __float2half_rn(a0), h1 = __float2half_rn(a1);
            __half h2 = __float2half_rn(a2), h3 = __float2half_rn(a3);
            __half l0 = __float2half_rn(a0 - __half2float(h0));
            __half l1 = __float2half_rn(a1 - __half2float(h1));
            __half l2 = __float2half_rn(a2 - __half2float(h2));
            __half l3 = __float2half_rn(a3 - __half2float(h3));
            __half2* ph = (__half2*)&svH[d * 136 + j];
            ph[0] = __halves2half2(h0, h1); ph[1] = __halves2half2(h2, h3);
            __half2* pl = (__half2*)&svL[d * 136 + j];
            pl[0] = __halves2half2(l0, l1); pl[1] = __halves2half2(l2, l3);
        }

#pragma unroll
        for (int u = 0; u < 8; ++u) {
            const int flat = u * 256 + t;
            const int r = flat >> 4, c = (flat & 15) * 8;
            if (i0 + r < cntb) {
                uint4 praw = *(uint4*)&pS[r * 136 + c];
                __half2 p01 = *(__half2*)&praw.x, p23 = *(__half2*)&praw.y;
                __half2 p45 = *(__half2*)&praw.z, p67 = *(__half2*)&praw.w;
                float2 f0 = __half22float2(p01), f1 = __half22float2(p23);
                float2 f2 = __half22float2(p45), f3 = __half22float2(p67);
                float4 w0, w1;
                w0.x = f0.x * scaleS[c + 0]; w0.y = f0.y * scaleS[c + 1];
                w0.z = f1.x * scaleS[c + 2]; w0.w = f1.y * scaleS[c + 3];
                w1.x = f2.x * scaleS[c + 4]; w1.y = f2.y * scaleS[c + 5];
                w1.z = f3.x * scaleS[c + 6]; w1.w = f3.y * scaleS[c + 7];
                float* dst = &aB[(size_t)idxS[r] * SS + j0 + c];
                *(float4*)dst       = w0;
                *(float4*)(dst + 4) = w1;
            }
        }
        __syncthreads();

        const uint32_t pSb = smb + (uint32_t)(FO_P + buf * FO_PB);
#pragma unroll
        for (int k16 = 0; k16 < 128; k16 += 16) {
            uint32_t ap[4][4], bh[4], bl[4];
#pragma unroll
            for (int mt = 0; mt < 4; ++mt) {
                const uint32_t adr = pSb +
                    (uint32_t)(((aRow + mt * 16) * 136 + k16 + aK) * 2);
                LDSM4(ap[mt], adr);
            }
            const uint32_t badr = smb +
                (uint32_t)(FO_SVH + (bRow * 136 + k16 + bK) * 2);
            LDSM4(bh, badr);
            LDSM4(bl, badr + (FO_SVL - FO_SVH));
#pragma unroll
            for (int mt = 0; mt < 4; ++mt)
#pragma unroll
                for (int nt = 0; nt < 2; ++nt) {
                    const uint32_t bhf[2] = { bh[nt * 2], bh[nt * 2 + 1] };
                    const uint32_t blf[2] = { bl[nt * 2], bl[nt * 2 + 1] };
                    hmma16816(acc[mt][nt], ap[mt], bhf);
                    hmma16816(acc[mt][nt], ap[mt], blf);
                }
        }
    }

#pragma unroll
    for (int mt = 0; mt < 4; ++mt) {
        const int ci = i0 + warpM * 64 + mt * 16 + (lane >> 2);
#pragma unroll
        for (int nt = 0; nt < 2; ++nt) {
            const int d = warpN * 16 + nt * 8 + (lane & 3) * 2;
            if (ci < cntb) {
                float2 v0; v0.x = acc[mt][nt][0]; v0.y = acc[mt][nt][1];
                *(float2*)&Out[((size_t)b * SS + idxS[ci - i0]) * ZZ + d] = v0;
            }
            if (ci + 8 < cntb) {
                float2 v8; v8.x = acc[mt][nt][2]; v8.y = acc[mt][nt][3];
                *(float2*)&Out[((size_t)b * SS + idxS[ci + 8 - i0]) * ZZ + d] = v8;
            }
        }
    }
}

// ============================== launch ======================================
extern "C" void kernel_launch(void* const* d_in, const int* in_sizes, int n_in,
                              void* d_out, int out_size)
{
    const float* enc  = (const float*)d_in[0];
    const float* dec  = (const float*)d_in[1];
    const float* lat  = (const float*)d_in[3];
    const void*  mask = d_in[4];
    const float* Wq   = (const float*)d_in[5];
    const float* Wk   = (const float*)d_in[6];
    const float* Wv   = (const float*)d_in[7];

    float* outp = (float*)d_out;

    const size_t OUTE = (size_t)BB * SS * ZZ;
    const size_t ATTE = (size_t)BB * SS * SS;

    float  *vtp, *cmaxp, *rcsp, *pmaxp, *psump, *attfb;
    __half *GThi, *GTlo, *ehi, *elo, *qhi, *qlo, *pattp;
    int *idxp, *cntp;
    cudaGetSymbolAddress((void**)&GThi,  g_GThi);
    cudaGetSymbolAddress((void**)&GTlo,  g_GTlo);
    cudaGetSymbolAddress((void**)&ehi,   g_ehi);
    cudaGetSymbolAddress((void**)&elo,   g_elo);
    cudaGetSymbolAddress((void**)&qhi,   g_qhi);
    cudaGetSymbolAddress((void**)&qlo,   g_qlo);
    cudaGetSymbolAddress((void**)&vtp,   g_vT);
    cudaGetSymbolAddress((void**)&pattp, g_patt);
    cudaGetSymbolAddress((void**)&pmaxp, g_pmax);
    cudaGetSymbolAddress((void**)&psump, g_psum);
    cudaGetSymbolAddress((void**)&cmaxp, g_cmax);
    cudaGetSymbolAddress((void**)&rcsp,  g_rcs);
    cudaGetSymbolAddress((void**)&idxp,  g_idx);
    cudaGetSymbolAddress((void**)&cntp,  g_cnt);
    cudaGetSymbolAddress((void**)&attfb, g_att);

    float* attnbuf = ((size_t)out_size >= OUTE + ATTE) ? (outp + OUTE) : attfb;

    const int M = BB * SS;   // 65536

    static int inited = 0;
    static cudaStream_t s1, s2, s3;
    static cudaEvent_t evF, ev1, ev2, ev3;
    if (!inited) {
        cudaFuncSetAttribute(align_mma_kernel,
                             cudaFuncAttributeMaxDynamicSharedMemorySize, 81920);
        cudaFuncSetAttribute(qproj_kernel,
                             cudaFuncAttributeMaxDynamicSharedMemorySize, 98304);
        cudaFuncSetAttribute(fused_out_mma_kernel,
                             cudaFuncAttributeMaxDynamicSharedMemorySize, FO_TOTAL);
        cudaStreamCreateWithFlags(&s1, cudaStreamNonBlocking);
        cudaStreamCreateWithFlags(&s2, cudaStreamNonBlocking);
        cudaStreamCreateWithFlags(&s3, cudaStreamNonBlocking);
        cudaEventCreateWithFlags(&evF, cudaEventDisableTiming);
        cudaEventCreateWithFlags(&ev1, cudaEventDisableTiming);
        cudaEventCreateWithFlags(&ev2, cudaEventDisableTiming);
        cudaEventCreateWithFlags(&ev3, cudaEventDisableTiming);
        inited = 1;
    }

    // ---- fork side streams off the main (capture) stream ----
    cudaEventRecord(evF, 0);
    cudaStreamWaitEvent(s1, evF, 0);
    cudaStreamWaitEvent(s2, evF, 0);
    cudaStreamWaitEvent(s3, evF, 0);

    // s1: GT = Wk @ Wq^T, split fp16  (needed by qproj)
    gmatsplit_kernel<<<dim3(4, 4), 256, 0, s1>>>(Wk, Wq, GThi, GTlo);
    cudaEventRecord(ev1, s1);

    // s2: enc split  (needed by align)
    split_kernel<<<592, 256, 0, s2>>>(enc, ehi, elo, M * HH / 4);
    cudaEventRecord(ev2, s2);

    // s3: vT + zerofill  (needed by fused_out)
    vprojtrans_kernel<<<M / 32, 256, 0, s3>>>(lat, Wv, vtp);
    zerofill_kernel<<<dim3(SS, BB), 256, 0, s3>>>(mask, attnbuf, outp);
    cudaEventRecord(ev3, s3);

    // ---- main stream: critical path ----
    compact_kernel<<<BB, 256>>>(mask, idxp, cntp);

    cudaStreamWaitEvent(0, ev1, 0);
    // q' = gathered dec @ GT^T (fused gather+split+HMMA)
    qproj_kernel<<<dim3(HH / 128, M / 128), 256, 98304>>>(
        dec, idxp, cntp, GThi, GTlo, qhi, qlo);

    cudaStreamWaitEvent(0, ev2, 0);
    // p = exp(masked-scaled logits - tilemax), compact rows only
    align_mma_kernel<<<dim3(SS / 128, SS / 128, BB), 256, 81920>>>(
        qhi, qlo, ehi, elo, cntp, pattp, pmaxp, psump);

    combine_kernel<<<(BB * SS) / 256, 256>>>(pmaxp, psump, cmaxp, rcsp);

    cudaStreamWaitEvent(0, ev3, 0);
    fused_out_mma_kernel<<<dim3(SS / 128, BB), 256, FO_TOTAL>>>(
        pattp, vtp, pmaxp, cmaxp, rcsp, idxp, cntp, attnbuf, outp);
}